// round 14
// baseline (speedup 1.0000x reference)
#include <cuda_runtime.h>
#include <cuda_fp16.h>

#define LUT5 59049      // 9^5
#define HW   (1024*1024)
#define NPIX (4*HW)

#define BLK     512         // 8^3 base-index blocks over dims 2,3,4
#define NENT    (81*BLK)    // 41472 entries (9x9 grid over dims 0,1)
// Entry: 40 fp16 (5 ch x 8 corners of dims 2,3,4), padded to 128B stride (one line).
// Half index within entry: c*8 + t, t = c2*4 + c3*2 + c4. Halves 40..63 unused (zero).
__device__ __align__(128) __half g_D[NENT * 64];   // 5.3 MB

// One thread per (entry, channel, half2-chunk): 829K threads for MLP/latency hiding.
// t2 = c2*2 + c3 indexes the half2 pair along c4. Scalar loads only (lut + c*59049
// is 4B-aligned, 59049 odd). Stores: consecutive threads write consecutive 4B words.
__global__ void pack_kernel(const float* __restrict__ lut) {
    int tid = blockIdx.x * blockDim.x + threadIdx.x;
    if (tid >= NENT * 20) return;
    int e  = tid / 20;
    int r  = tid - e * 20;
    int c  = r >> 2;
    int t2 = r & 3;
    int i01 = e >> 9;            // 0..80
    int rem = e & 511;
    int b2 = rem >> 6, b3 = (rem >> 3) & 7, b4 = rem & 7;
    int i0 = i01 / 9, i1 = i01 - (i01 / 9) * 9;
    const float* src = lut + c * LUT5 + i0 * 6561 + i1 * 729 + b2 * 81 + b3 * 9 + b4
                     + (t2 >> 1) * 81 + (t2 & 1) * 9;
    __half2 h = __floats2half2_rn(src[0], src[1]);
    *(unsigned*)((char*)g_D + (size_t)e * 128 + c * 16 + t2 * 4) = *(unsigned*)&h;
}

__device__ __forceinline__ float dot8h(uint4 q, __half2 w0, __half2 w1,
                                       __half2 w2, __half2 w3) {
    __half2 s = __hmul2(*(const __half2*)&q.x, w0);
    s = __hfma2(*(const __half2*)&q.y, w1, s);
    s = __hfma2(*(const __half2*)&q.z, w2, s);
    s = __hfma2(*(const __half2*)&q.w, w3, s);
    float2 f = __half22float2(s);
    return f.x + f.y;
}

// Warp owns 32 consecutive pixels. Coalesced load of 5 channel planes (1 line each),
// 6 compute batches of 5-lane groups; per-batch broadcast is 3 packed shfls
// (ent|fr4, half2(fr0,fr1), half2(fr2,fr3)); smem scatter; coalesced stores.
__global__ void __launch_bounds__(256)
lut_kernel(const float* __restrict__ x, float* __restrict__ out) {
    const unsigned FULL = 0xffffffffu;
    __shared__ float sout[8][160];           // per-warp: 32 px x 5 ch
    int lane = threadIdx.x & 31;
    int wrp  = (threadIdx.x >> 5) & 7;
    int gw   = (blockIdx.x * blockDim.x + threadIdx.x) >> 5;
    int p    = gw * 32 + lane;              // this lane's owned pixel
    int b    = p >> 20;
    int hw   = p & (HW - 1);
    size_t iobase = (size_t)b * 5 * HW + hw;   // warp-aligned: hw ≡ lane (mod 32)

    // ---- owner lane: per-pixel params packed into 3 registers ----
    unsigned r_ef, r01, r23;
    {
        float xs0 = fminf(fmaxf(x[iobase + 0 * (size_t)HW] * 8.0f, 0.0f), 7.9999995f);
        float xs1 = fminf(fmaxf(x[iobase + 1 * (size_t)HW] * 8.0f, 0.0f), 7.9999995f);
        float xs2 = fminf(fmaxf(x[iobase + 2 * (size_t)HW] * 8.0f, 0.0f), 7.9999995f);
        float xs3 = fminf(fmaxf(x[iobase + 3 * (size_t)HW] * 8.0f, 0.0f), 7.9999995f);
        float xs4 = fminf(fmaxf(x[iobase + 4 * (size_t)HW] * 8.0f, 0.0f), 7.9999995f);

        float f0 = floorf(xs0), f1 = floorf(xs1), f2 = floorf(xs2),
              f3 = floorf(xs3), f4 = floorf(xs4);
        int i0 = (int)f0, i1 = (int)f1, i2 = (int)f2, i3 = (int)f3, i4 = (int)f4;
        int ent = ((i0 * 9 + i1) << 9) + (i2 << 6) + (i3 << 3) + i4;  // < 41472

        __half2 p01 = __floats2half2_rn(xs0 - f0, xs1 - f1);
        __half2 p23 = __floats2half2_rn(xs2 - f2, xs3 - f3);
        __half  h4  = __float2half_rn(xs4 - f4);

        r_ef = ((unsigned)ent << 16) | (unsigned)__half_as_ushort(h4);
        r01  = *(unsigned*)&p01;
        r23  = *(unsigned*)&p23;
    }

    int g  = lane / 5; if (g > 5) g = 5;    // compute group 0..5
    int ch = lane - g * 5;
    int che = ch > 4 ? 4 : ch;

    const uint4* Dq = (const uint4*)g_D;

#pragma unroll
    for (int k = 0; k < 6; k++) {
        int q = 6 * k + g;                   // pixel-in-warp this group handles
        bool active = (q < 32) && (ch < 5);  // batch 5: groups 0,1 only; lanes 30/31 never
        int qs = q < 32 ? q : 31;

        unsigned bef = __shfl_sync(FULL, r_ef, qs);
        unsigned b01 = __shfl_sync(FULL, r01,  qs);
        unsigned b23 = __shfl_sync(FULL, r23,  qs);

        int ent = (int)(bef >> 16);
        float fr4 = __half2float(__ushort_as_half((unsigned short)(bef & 0xffffu)));
        float2 f01 = __half22float2(*(__half2*)&b01);   // fr0, fr1
        float2 f23 = __half22float2(*(__half2*)&b23);   // fr2, fr3

        float w0a = 1.0f - f01.x, w0b = f01.x;
        float w1a = 1.0f - f01.y, w1b = f01.y;
        float w2a = 1.0f - f23.x, w2b = f23.x;
        float w3a = 1.0f - f23.y, w3b = f23.y;
        float w4a = 1.0f - fr4,   w4b = fr4;

        float pw0 = w0a * w1a, pw1 = w0a * w1b, pw2 = w0b * w1a, pw3 = w0b * w1b;
        float t0 = w2a * w3a, t1 = w2a * w3b, t2 = w2b * w3a, t3 = w2b * w3b;

        __half2 cw0 = __floats2half2_rn(t0 * w4a, t0 * w4b);
        __half2 cw1 = __floats2half2_rn(t1 * w4a, t1 * w4b);
        __half2 cw2 = __floats2half2_rn(t2 * w4a, t2 * w4b);
        __half2 cw3 = __floats2half2_rn(t3 * w4a, t3 * w4b);

        if (active) {
            uint4 q0 = Dq[(ent)            * 8 + che];
            uint4 q1 = Dq[(ent + BLK)      * 8 + che];
            uint4 q2 = Dq[(ent + 9 * BLK)  * 8 + che];
            uint4 q3 = Dq[(ent + 10 * BLK) * 8 + che];
            float acc;
            acc = pw0 * dot8h(q0, cw0, cw1, cw2, cw3);
            acc = fmaf(pw1, dot8h(q1, cw0, cw1, cw2, cw3), acc);
            acc = fmaf(pw2, dot8h(q2, cw0, cw1, cw2, cw3), acc);
            acc = fmaf(pw3, dot8h(q3, cw0, cw1, cw2, cw3), acc);
            // addr = q*5 + ch = 30k + lane -> consecutive, conflict-free
            sout[wrp][30 * k + lane] = acc;
        }
    }

    __syncwarp(FULL);

    // Coalesced stores: lane reads its pixel's 5 channels (stride 5 ⊥ 32 banks).
    out[iobase + 0 * (size_t)HW] = sout[wrp][lane * 5 + 0];
    out[iobase + 1 * (size_t)HW] = sout[wrp][lane * 5 + 1];
    out[iobase + 2 * (size_t)HW] = sout[wrp][lane * 5 + 2];
    out[iobase + 3 * (size_t)HW] = sout[wrp][lane * 5 + 3];
    out[iobase + 4 * (size_t)HW] = sout[wrp][lane * 5 + 4];
}

extern "C" void kernel_launch(void* const* d_in, const int* in_sizes, int n_in,
                              void* d_out, int out_size) {
    const float* x   = (const float*)d_in[0];
    const float* lut = (const float*)d_in[1];
    if (n_in >= 2 && in_sizes[0] == 5 * LUT5) {
        lut = (const float*)d_in[0];
        x   = (const float*)d_in[1];
    }
    float* out = (float*)d_out;

    pack_kernel<<<(NENT * 20 + 255) / 256, 256>>>(lut);

    int blocks = NPIX / (32 * 8);   // 32 px/warp, 8 warps/block
    lut_kernel<<<blocks, 256>>>(x, out);
}

// round 15
// speedup vs baseline: 1.0097x; 1.0097x over previous
#include <cuda_runtime.h>
#include <cuda_fp16.h>

#define LUT5 59049      // 9^5
#define HW   (1024*1024)
#define NPIX (4*HW)

#define BLK     512         // 8^3 base-index blocks over dims 2,3,4
#define NENT    (81*BLK)    // 41472 entries (9x9 grid over dims 0,1)
// Entry: 40 fp16 (5 ch x 8 corners of dims 2,3,4), padded to 128B stride (one line).
// Half index within entry: c*8 + t, t = c2*4 + c3*2 + c4. Halves 40..63 unused (zero).
__device__ __align__(128) __half g_D[NENT * 64];   // 5.3 MB

// Warp-cooperative pack: one warp per (c, i01, b2, b3) handles the 8 entries
// (b4 = 0..7). Source window = 36 floats in two contiguous 18-float segments.
// Lane l: entry b4 = l>>2, component j = l&3 (j indexes offsets {0,9,81,90});
// value pair = segment[hi][s], segment[hi][s+1] with s = b4 + (j&1)*9, hi = j>=2.
__global__ void pack_kernel(const float* __restrict__ lut) {
    const unsigned FULL = 0xffffffffu;
    int w = (blockIdx.x * blockDim.x + threadIdx.x) >> 5;   // 0..25919
    if (w >= 5 * 81 * 64) return;
    int lane = threadIdx.x & 31;
    int c    = w % 5;
    int rest = w / 5;            // i01*64 + b2*8 + b3
    int i01  = rest >> 6;
    int b2   = (rest >> 3) & 7;
    int b3   = rest & 7;
    int i0 = i01 / 9, i1 = i01 - (i01 / 9) * 9;

    int base = c * LUT5 + i0 * 6561 + i1 * 729 + b2 * 81 + b3 * 9;
    float f1 = (lane < 18) ? lut[base + lane]      : 0.0f;   // offsets 0..17
    float f2 = (lane < 18) ? lut[base + 81 + lane] : 0.0f;   // offsets 81..98

    int b4 = lane >> 2;
    int j  = lane & 3;
    int s  = b4 + (j & 1) * 9;          // 0..16
    bool hi = (j & 2) != 0;

    float a1 = __shfl_sync(FULL, f1, s);
    float a2 = __shfl_sync(FULL, f2, s);
    float b1 = __shfl_sync(FULL, f1, s + 1);
    float b2v = __shfl_sync(FULL, f2, s + 1);
    float v0 = hi ? a2 : a1;
    float v1 = hi ? b2v : b1;

    __half2 h = __floats2half2_rn(v0, v1);
    int eBase = (i01 << 9) + (b2 << 6) + (b3 << 3);   // + b4
    *(unsigned*)((char*)g_D + (size_t)(eBase + b4) * 128 + c * 16 + j * 4)
        = *(unsigned*)&h;
}

__device__ __forceinline__ float dot8h(uint4 q, __half2 w0, __half2 w1,
                                       __half2 w2, __half2 w3) {
    __half2 s = __hmul2(*(const __half2*)&q.x, w0);
    s = __hfma2(*(const __half2*)&q.y, w1, s);
    s = __hfma2(*(const __half2*)&q.z, w2, s);
    s = __hfma2(*(const __half2*)&q.w, w3, s);
    float2 f = __half22float2(s);
    return f.x + f.y;
}

// Warp owns 32 consecutive pixels. Coalesced load of 5 channel planes (1 line each),
// 6 compute batches of 5-lane groups; per-batch broadcast is 3 packed shfls
// (ent|fr4, half2(fr0,fr1), half2(fr2,fr3)); smem scatter; coalesced stores.
__global__ void __launch_bounds__(256)
lut_kernel(const float* __restrict__ x, float* __restrict__ out) {
    const unsigned FULL = 0xffffffffu;
    __shared__ float sout[8][160];           // per-warp: 32 px x 5 ch
    int lane = threadIdx.x & 31;
    int wrp  = (threadIdx.x >> 5) & 7;
    int gw   = (blockIdx.x * blockDim.x + threadIdx.x) >> 5;
    int p    = gw * 32 + lane;              // this lane's owned pixel
    int b    = p >> 20;
    int hw   = p & (HW - 1);
    size_t iobase = (size_t)b * 5 * HW + hw;   // warp-aligned: hw ≡ lane (mod 32)

    // ---- owner lane: per-pixel params packed into 3 registers ----
    unsigned r_ef, r01, r23;
    {
        float xs0 = fminf(fmaxf(x[iobase + 0 * (size_t)HW] * 8.0f, 0.0f), 7.9999995f);
        float xs1 = fminf(fmaxf(x[iobase + 1 * (size_t)HW] * 8.0f, 0.0f), 7.9999995f);
        float xs2 = fminf(fmaxf(x[iobase + 2 * (size_t)HW] * 8.0f, 0.0f), 7.9999995f);
        float xs3 = fminf(fmaxf(x[iobase + 3 * (size_t)HW] * 8.0f, 0.0f), 7.9999995f);
        float xs4 = fminf(fmaxf(x[iobase + 4 * (size_t)HW] * 8.0f, 0.0f), 7.9999995f);

        float f0 = floorf(xs0), f1 = floorf(xs1), f2 = floorf(xs2),
              f3 = floorf(xs3), f4 = floorf(xs4);
        int i0 = (int)f0, i1 = (int)f1, i2 = (int)f2, i3 = (int)f3, i4 = (int)f4;
        int ent = ((i0 * 9 + i1) << 9) + (i2 << 6) + (i3 << 3) + i4;  // < 41472

        __half2 p01 = __floats2half2_rn(xs0 - f0, xs1 - f1);
        __half2 p23 = __floats2half2_rn(xs2 - f2, xs3 - f3);
        __half  h4  = __float2half_rn(xs4 - f4);

        r_ef = ((unsigned)ent << 16) | (unsigned)__half_as_ushort(h4);
        r01  = *(unsigned*)&p01;
        r23  = *(unsigned*)&p23;
    }

    int g  = lane / 5; if (g > 5) g = 5;    // compute group 0..5
    int ch = lane - g * 5;
    int che = ch > 4 ? 4 : ch;

    const uint4* Dq = (const uint4*)g_D;

#pragma unroll
    for (int k = 0; k < 6; k++) {
        int q = 6 * k + g;                   // pixel-in-warp this group handles
        // k<5 -> q = 6k+g <= 29 < 32 always; only batch 5 needs the range check.
        bool inrange = (k < 5) || (g < 2);
        bool active  = inrange && (ch < 5);
        int qs = inrange ? q : 31;

        unsigned bef = __shfl_sync(FULL, r_ef, qs);
        unsigned b01 = __shfl_sync(FULL, r01,  qs);
        unsigned b23 = __shfl_sync(FULL, r23,  qs);

        int ent = (int)(bef >> 16);
        float fr4 = __half2float(__ushort_as_half((unsigned short)(bef & 0xffffu)));
        float2 f01 = __half22float2(*(__half2*)&b01);   // fr0, fr1
        float2 f23 = __half22float2(*(__half2*)&b23);   // fr2, fr3

        float w0a = 1.0f - f01.x, w0b = f01.x;
        float w1a = 1.0f - f01.y, w1b = f01.y;
        float w2a = 1.0f - f23.x, w2b = f23.x;
        float w3a = 1.0f - f23.y, w3b = f23.y;
        float w4a = 1.0f - fr4,   w4b = fr4;

        float pw0 = w0a * w1a, pw1 = w0a * w1b, pw2 = w0b * w1a, pw3 = w0b * w1b;
        float t0 = w2a * w3a, t1 = w2a * w3b, t2 = w2b * w3a, t3 = w2b * w3b;

        __half2 cw0 = __floats2half2_rn(t0 * w4a, t0 * w4b);
        __half2 cw1 = __floats2half2_rn(t1 * w4a, t1 * w4b);
        __half2 cw2 = __floats2half2_rn(t2 * w4a, t2 * w4b);
        __half2 cw3 = __floats2half2_rn(t3 * w4a, t3 * w4b);

        if (active) {
            uint4 q0 = Dq[(ent)            * 8 + che];
            uint4 q1 = Dq[(ent + BLK)      * 8 + che];
            uint4 q2 = Dq[(ent + 9 * BLK)  * 8 + che];
            uint4 q3 = Dq[(ent + 10 * BLK) * 8 + che];
            float acc;
            acc = pw0 * dot8h(q0, cw0, cw1, cw2, cw3);
            acc = fmaf(pw1, dot8h(q1, cw0, cw1, cw2, cw3), acc);
            acc = fmaf(pw2, dot8h(q2, cw0, cw1, cw2, cw3), acc);
            acc = fmaf(pw3, dot8h(q3, cw0, cw1, cw2, cw3), acc);
            // addr = q*5 + ch = 30k + lane -> consecutive, conflict-free
            sout[wrp][30 * k + lane] = acc;
        }
    }

    __syncwarp(FULL);

    // Coalesced stores: lane reads its pixel's 5 channels (stride 5 ⊥ 32 banks).
    out[iobase + 0 * (size_t)HW] = sout[wrp][lane * 5 + 0];
    out[iobase + 1 * (size_t)HW] = sout[wrp][lane * 5 + 1];
    out[iobase + 2 * (size_t)HW] = sout[wrp][lane * 5 + 2];
    out[iobase + 3 * (size_t)HW] = sout[wrp][lane * 5 + 3];
    out[iobase + 4 * (size_t)HW] = sout[wrp][lane * 5 + 4];
}

extern "C" void kernel_launch(void* const* d_in, const int* in_sizes, int n_in,
                              void* d_out, int out_size) {
    const float* x   = (const float*)d_in[0];
    const float* lut = (const float*)d_in[1];
    if (n_in >= 2 && in_sizes[0] == 5 * LUT5) {
        lut = (const float*)d_in[0];
        x   = (const float*)d_in[1];
    }
    float* out = (float*)d_out;

    int pack_warps = 5 * 81 * 64;                 // 25920 warps
    pack_kernel<<<(pack_warps * 32 + 255) / 256, 256>>>(lut);

    int blocks = NPIX / (32 * 8);   // 32 px/warp, 8 warps/block
    lut_kernel<<<blocks, 256>>>(x, out);
}

// round 16
// speedup vs baseline: 1.0479x; 1.0378x over previous
#include <cuda_runtime.h>
#include <cuda_fp16.h>

#define LUT5 59049      // 9^5
#define HW   (1024*1024)
#define NPIX (4*HW)

#define BLK     512         // 8^3 base-index blocks over dims 2,3,4
#define NENT    (81*BLK)    // 41472 entries (9x9 grid over dims 0,1)
// Entry: 40 fp16 (5 ch x 8 corners of dims 2,3,4), padded to 128B stride (one line).
// Half index within entry: c*8 + t, t = c2*4 + c3*2 + c4. Halves 40..63 unused (zero).
__device__ __align__(128) __half g_D[NENT * 64];   // 5.3 MB

// R13 pack (best measured): one thread per (e, c), c fastest. Scalar loads only:
// lut + c*59049 is 4B-aligned (59049 odd), vector loads would fault for odd c.
__global__ void pack_kernel(const float* __restrict__ lut) {
    int tid = blockIdx.x * blockDim.x + threadIdx.x;
    if (tid >= NENT * 5) return;
    int e = tid / 5;
    int c = tid - e * 5;
    int i01 = e >> 9;            // 0..80
    int rem = e & 511;
    int b2 = rem >> 6, b3 = (rem >> 3) & 7, b4 = rem & 7;
    int i0 = i01 / 9, i1 = i01 - (i01 / 9) * 9;
    const float* src = lut + c * LUT5 + i0 * 6561 + i1 * 729 + b2 * 81 + b3 * 9 + b4;

    __half2 h0 = __floats2half2_rn(src[0],  src[1]);    // c2=0 c3=0
    __half2 h1 = __floats2half2_rn(src[9],  src[10]);   // c2=0 c3=1
    __half2 h2 = __floats2half2_rn(src[81], src[82]);   // c2=1 c3=0
    __half2 h3 = __floats2half2_rn(src[90], src[91]);   // c2=1 c3=1

    uint4 v;
    v.x = *(unsigned*)&h0;  v.y = *(unsigned*)&h1;
    v.z = *(unsigned*)&h2;  v.w = *(unsigned*)&h3;
    *(uint4*)(g_D + (size_t)e * 64 + c * 8) = v;   // 16B-aligned dst
}

__device__ __forceinline__ float dot8h(uint4 q, __half2 w0, __half2 w1,
                                       __half2 w2, __half2 w3) {
    __half2 s = __hmul2(*(const __half2*)&q.x, w0);
    s = __hfma2(*(const __half2*)&q.y, w1, s);
    s = __hfma2(*(const __half2*)&q.z, w2, s);
    s = __hfma2(*(const __half2*)&q.w, w3, s);
    float2 f = __half22float2(s);
    return f.x + f.y;
}

// Warp owns 32 consecutive pixels. Coalesced I/O. Exact task partition:
// 160 (px,ch) tasks in 5 batches of 32 lanes — zero idle lanes, no predicates.
// Per-batch: 3 packed per-lane shfls fetch the task pixel's params.
__global__ void __launch_bounds__(256)
lut_kernel(const float* __restrict__ x, float* __restrict__ out) {
    const unsigned FULL = 0xffffffffu;
    __shared__ float sout[8][160];           // per-warp: 32 px x 5 ch
    int lane = threadIdx.x & 31;
    int wrp  = (threadIdx.x >> 5) & 7;
    int gw   = (blockIdx.x * blockDim.x + threadIdx.x) >> 5;
    int p    = gw * 32 + lane;              // this lane's owned pixel
    int b    = p >> 20;
    int hw   = p & (HW - 1);
    size_t iobase = (size_t)b * 5 * HW + hw;   // warp-aligned: hw ≡ lane (mod 32)

    // ---- owner lane: per-pixel params packed into 3 registers ----
    unsigned r_ef, r01, r23;
    {
        float xs0 = fminf(fmaxf(x[iobase + 0 * (size_t)HW] * 8.0f, 0.0f), 7.9999995f);
        float xs1 = fminf(fmaxf(x[iobase + 1 * (size_t)HW] * 8.0f, 0.0f), 7.9999995f);
        float xs2 = fminf(fmaxf(x[iobase + 2 * (size_t)HW] * 8.0f, 0.0f), 7.9999995f);
        float xs3 = fminf(fmaxf(x[iobase + 3 * (size_t)HW] * 8.0f, 0.0f), 7.9999995f);
        float xs4 = fminf(fmaxf(x[iobase + 4 * (size_t)HW] * 8.0f, 0.0f), 7.9999995f);

        float f0 = floorf(xs0), f1 = floorf(xs1), f2 = floorf(xs2),
              f3 = floorf(xs3), f4 = floorf(xs4);
        int i0 = (int)f0, i1 = (int)f1, i2 = (int)f2, i3 = (int)f3, i4 = (int)f4;
        int ent = ((i0 * 9 + i1) << 9) + (i2 << 6) + (i3 << 3) + i4;  // < 41472

        __half2 p01 = __floats2half2_rn(xs0 - f0, xs1 - f1);
        __half2 p23 = __floats2half2_rn(xs2 - f2, xs3 - f3);
        __half  h4  = __float2half_rn(xs4 - f4);

        r_ef = ((unsigned)ent << 16) | (unsigned)__half_as_ushort(h4);
        r01  = *(unsigned*)&p01;
        r23  = *(unsigned*)&p23;
    }

    const uint4* Dq = (const uint4*)g_D;

#pragma unroll
    for (int k = 0; k < 5; k++) {
        int t  = 32 * k + lane;              // task id: px*5 + ch
        int px = t / 5;                      // pixel-in-warp (0..31)
        int ch = t - px * 5;                 // channel (0..4)

        unsigned bef = __shfl_sync(FULL, r_ef, px);
        unsigned b01 = __shfl_sync(FULL, r01,  px);
        unsigned b23 = __shfl_sync(FULL, r23,  px);

        int ent = (int)(bef >> 16);
        float fr4 = __half2float(__ushort_as_half((unsigned short)(bef & 0xffffu)));
        float2 f01 = __half22float2(*(__half2*)&b01);   // fr0, fr1
        float2 f23 = __half22float2(*(__half2*)&b23);   // fr2, fr3

        float w0a = 1.0f - f01.x, w0b = f01.x;
        float w1a = 1.0f - f01.y, w1b = f01.y;
        float w2a = 1.0f - f23.x, w2b = f23.x;
        float w3a = 1.0f - f23.y, w3b = f23.y;
        float w4a = 1.0f - fr4,   w4b = fr4;

        float pw0 = w0a * w1a, pw1 = w0a * w1b, pw2 = w0b * w1a, pw3 = w0b * w1b;
        float t0 = w2a * w3a, t1 = w2a * w3b, t2 = w2b * w3a, t3 = w2b * w3b;

        __half2 cw0 = __floats2half2_rn(t0 * w4a, t0 * w4b);
        __half2 cw1 = __floats2half2_rn(t1 * w4a, t1 * w4b);
        __half2 cw2 = __floats2half2_rn(t2 * w4a, t2 * w4b);
        __half2 cw3 = __floats2half2_rn(t3 * w4a, t3 * w4b);

        uint4 q0 = Dq[(ent)            * 8 + ch];
        uint4 q1 = Dq[(ent + BLK)      * 8 + ch];
        uint4 q2 = Dq[(ent + 9 * BLK)  * 8 + ch];
        uint4 q3 = Dq[(ent + 10 * BLK) * 8 + ch];
        float acc;
        acc = pw0 * dot8h(q0, cw0, cw1, cw2, cw3);
        acc = fmaf(pw1, dot8h(q1, cw0, cw1, cw2, cw3), acc);
        acc = fmaf(pw2, dot8h(q2, cw0, cw1, cw2, cw3), acc);
        acc = fmaf(pw3, dot8h(q3, cw0, cw1, cw2, cw3), acc);

        sout[wrp][t] = acc;                  // consecutive -> conflict-free
    }

    __syncwarp(FULL);

    // Coalesced stores: lane reads its pixel's 5 channels (stride 5 ⊥ 32 banks).
    out[iobase + 0 * (size_t)HW] = sout[wrp][lane * 5 + 0];
    out[iobase + 1 * (size_t)HW] = sout[wrp][lane * 5 + 1];
    out[iobase + 2 * (size_t)HW] = sout[wrp][lane * 5 + 2];
    out[iobase + 3 * (size_t)HW] = sout[wrp][lane * 5 + 3];
    out[iobase + 4 * (size_t)HW] = sout[wrp][lane * 5 + 4];
}

extern "C" void kernel_launch(void* const* d_in, const int* in_sizes, int n_in,
                              void* d_out, int out_size) {
    const float* x   = (const float*)d_in[0];
    const float* lut = (const float*)d_in[1];
    if (n_in >= 2 && in_sizes[0] == 5 * LUT5) {
        lut = (const float*)d_in[0];
        x   = (const float*)d_in[1];
    }
    float* out = (float*)d_out;

    pack_kernel<<<(NENT * 5 + 255) / 256, 256>>>(lut);

    int blocks = NPIX / (32 * 8);   // 32 px/warp, 8 warps/block
    lut_kernel<<<blocks, 256>>>(x, out);
}